// round 9
// baseline (speedup 1.0000x reference)
#include <cuda_runtime.h>
#include <cstdint>

// Problem shape (fixed by the dataset)
#define BB 16
#define NN 512
#define FF 256
#define M_TOT (BB * NN)   // 8192

typedef unsigned long long ull;

// Scratch
__device__ float g_y[M_TOT * FF];      // adj @ x
__device__ float g_deg[M_TOT];         // rowsum(adj)

// ---- packed f32x2 helpers ---------------------------------------------------
#define PACK_X2(d, lo, hi) \
    asm("mov.b64 %0, {%1, %2};" : "=l"(d) : "r"(__float_as_uint(lo)), "r"(__float_as_uint(hi)))
#define UNPK_X2(lo, hi, s) do { unsigned _l, _h; \
    asm("mov.b64 {%0, %1}, %2;" : "=r"(_l), "=r"(_h) : "l"(s)); \
    lo = __uint_as_float(_l); hi = __uint_as_float(_h); } while (0)
#define ADD_X2I(acc, a) \
    asm("add.rn.f32x2 %0, %0, %1;" : "+l"(acc) : "l"(a))
#define FMA_X2I(acc, a, b) \
    asm("fma.rn.f32x2 %0, %1, %2, %0;" : "+l"(acc) : "l"(a), "l"(b))

// ---- cp.async helpers -------------------------------------------------------
__device__ __forceinline__ void cp_async16(unsigned saddr, const void* gptr) {
    asm volatile("cp.async.cg.shared.global [%0], [%1], 16;"
                 :: "r"(saddr), "l"(gptr));
}
#define CP_COMMIT() asm volatile("cp.async.commit_group;")
#define CP_WAIT(n)  asm volatile("cp.async.wait_group %0;" :: "n"(n))

// ---------------------------------------------------------------------------
// Kernel 1: y[b,i,f] = sum_j adj[b,i,j] * x[b,j,f]   deg[b,i] = rowsum
// Grid (NN/ICH, BB, 2): z = feature half. Warp owns 4 i-rows; lane owns 4
// features. x staged in 32-row double-buffered smem tiles via cp.async.
// adj row values for tile jt+1 prefetched during tile jt's drain (hides DRAM
// latency). Neighbor drain interleaves 4 independent row chains.
// ---------------------------------------------------------------------------
#define ICH 32
#define JT  32
#define FH  128
#define TILE_F4 (JT * FH / 4)     // 1024 float4 per tile
#define NTILES  (NN / JT)         // 16

__global__ __launch_bounds__(256) void agg_x_kernel(
    const float* __restrict__ X,
    const float* __restrict__ ADJ,
    float* __restrict__ Y,
    float* __restrict__ DEG)
{
    extern __shared__ float xt[];   // 2 * JT*FH floats = 32 KB

    const int b    = blockIdx.y;
    const int i0   = blockIdx.x * ICH;
    const int fs   = blockIdx.z;
    const int t    = threadIdx.x;
    const int w    = t >> 5;
    const int lane = t & 31;

    const float4* xb4 = reinterpret_cast<const float4*>(X + (size_t)b * NN * FF + fs * FH);
    const unsigned sbase = (unsigned)__cvta_generic_to_shared(xt);

    ull acc2[4][2] = {{0ull,0ull},{0ull,0ull},{0ull,0ull},{0ull,0ull}};
    int degc[4] = {0, 0, 0, 0};

    const float* adj_base = ADJ + ((size_t)b * NN + i0 + w * 4) * NN + lane;

    // issue x tile jt into buffer buf (4 x 16B per thread)
    auto issue = [&](int jt, int buf) {
#pragma unroll
        for (int p = 0; p < 4; p++) {
            int e   = t + p * 256;          // 0..1023
            int row = e >> 5;               // 0..31
            int c   = e & 31;               // float4 within row
            const float4* g = &xb4[(size_t)(jt * JT + row) * (FF / 4) + c];
            cp_async16(sbase + (unsigned)(buf * TILE_F4 + e) * 16u, g);
        }
        CP_COMMIT();
    };

    issue(0, 0);
    float av[4];
#pragma unroll
    for (int ii = 0; ii < 4; ii++)
        av[ii] = adj_base[(size_t)ii * NN];          // adj prefetch, tile 0

    for (int jt = 0; jt < NTILES; jt++) {
        const int buf = jt & 1;
        float avn[4] = {0.f, 0.f, 0.f, 0.f};
        if (jt + 1 < NTILES) {
            issue(jt + 1, buf ^ 1);
#pragma unroll
            for (int ii = 0; ii < 4; ii++)           // adj prefetch, next tile
                avn[ii] = adj_base[(size_t)ii * NN + (jt + 1) * JT];
            CP_WAIT(1);
        } else {
            CP_WAIT(0);
        }
        __syncthreads();

        unsigned m[4];
#pragma unroll
        for (int ii = 0; ii < 4; ii++) {
            m[ii] = __ballot_sync(0xffffffffu, av[ii] > 0.0f);
            degc[ii] += __popc(m[ii]);
        }

        const float* tb = xt + buf * (JT * FH) + lane * 4;
        while (m[0] | m[1] | m[2] | m[3]) {
#pragma unroll
            for (int ii = 0; ii < 4; ii++) {
                if (m[ii]) {
                    int j = __ffs(m[ii]) - 1;
                    m[ii] &= m[ii] - 1;
                    float4 h = *reinterpret_cast<const float4*>(tb + j * FH);
                    ull h01, h23;
                    PACK_X2(h01, h.x, h.y);
                    PACK_X2(h23, h.z, h.w);
                    ADD_X2I(acc2[ii][0], h01);
                    ADD_X2I(acc2[ii][1], h23);
                }
            }
        }
#pragma unroll
        for (int ii = 0; ii < 4; ii++) av[ii] = avn[ii];
        __syncthreads();
    }

#pragma unroll
    for (int ii = 0; ii < 4; ii++) {
        const int m_ = b * NN + i0 + w * 4 + ii;
        float4 o;
        UNPK_X2(o.x, o.y, acc2[ii][0]);
        UNPK_X2(o.z, o.w, acc2[ii][1]);
        *reinterpret_cast<float4*>(Y + (size_t)m_ * FF + fs * FH + lane * 4) = o;
        if (fs == 0 && lane == 0) DEG[m_] = (float)degc[ii];
    }
}

// ---------------------------------------------------------------------------
// Kernel 2: fully fused GEMM + gate + blend.
//   hp[m,n]  = leaky( sum_k y[m,k]*W[n,k] + deg[m]*bias[n], 0.2 )   (in regs)
//   coeff[m] = sigmoid( x[m,:].gwx + hp[m,:].gwh + gb )
//   out      = coeff*x + (1-coeff)*hp
// BM=32 (grid 256, 2 CTAs/SM), BN=256 (full row in one warp), BK=16.
// warp ty owns rows ty*4..+3; lane tx owns cols {tx*4..+3, 128+tx*4..+3}.
// Reg-prefetch double buffering over 16 k-tiles. FFMA2 inner product.
// ---------------------------------------------------------------------------
#define GBM 32
#define GBK 16

__global__ __launch_bounds__(256, 2) void gemm_fused_kernel(
    const float* __restrict__ Y,
    const float* __restrict__ W,
    const float* __restrict__ Wb,
    const float* __restrict__ DEG,
    const float* __restrict__ X,
    const float* __restrict__ GW,
    const float* __restrict__ GB,
    float* __restrict__ OUT)
{
    __shared__ float As[GBK][GBM];     // 2 KB
    __shared__ float Bs[GBK][FF];      // 16 KB

    const int t  = threadIdx.x;
    const int tx = t & 31;             // lane
    const int ty = t >> 5;             // warp
    const int m0 = blockIdx.x * GBM;

    const float4* Y4 = reinterpret_cast<const float4*>(Y);
    const float4* W4 = reinterpret_cast<const float4*>(W);

    // A prefetch: 32 rows x 4 float4 = 128 -> threads 0..127, 1 each
    const int ar = t >> 2, ac = t & 3;

    float4 pa;
    float4 pb[4];

    auto loadT = [&](int kt4) {      // kt4 = kt/4
        if (t < 128) pa = Y4[(size_t)(m0 + ar) * (FF / 4) + kt4 + ac];
#pragma unroll
        for (int p = 0; p < 4; p++) {
            int e = t + p * 256;
            pb[p] = W4[(size_t)(e >> 2) * (FF / 4) + kt4 + (e & 3)];
        }
    };
    auto storeT = [&]() {
        if (t < 128) {
            As[ac * 4 + 0][ar] = pa.x;
            As[ac * 4 + 1][ar] = pa.y;
            As[ac * 4 + 2][ar] = pa.z;
            As[ac * 4 + 3][ar] = pa.w;
        }
#pragma unroll
        for (int p = 0; p < 4; p++) {
            int e = t + p * 256;
            int n = e >> 2, c = e & 3;
            Bs[c * 4 + 0][n] = pb[p].x;
            Bs[c * 4 + 1][n] = pb[p].y;
            Bs[c * 4 + 2][n] = pb[p].z;
            Bs[c * 4 + 3][n] = pb[p].w;
        }
    };

    ull acc2[2][8];
#pragma unroll
    for (int p = 0; p < 2; p++)
#pragma unroll
        for (int j = 0; j < 8; j++) acc2[p][j] = 0ull;

    loadT(0);
    for (int kt = 0; kt < FF / GBK; kt++) {
        storeT();
        __syncthreads();
        if (kt + 1 < FF / GBK) loadT((kt + 1) * (GBK / 4));   // overlaps compute

#pragma unroll
        for (int k = 0; k < GBK; k++) {
            float4 a0 = *reinterpret_cast<const float4*>(&As[k][ty * 4]);
            float4 b0 = *reinterpret_cast<const float4*>(&Bs[k][tx * 4]);
            float4 b1 = *reinterpret_cast<const float4*>(&Bs[k][128 + tx * 4]);
            ull aa[2], bb[8];
            PACK_X2(aa[0], a0.x, a0.y);
            PACK_X2(aa[1], a0.z, a0.w);
            PACK_X2(bb[0], b0.x, b0.x);
            PACK_X2(bb[1], b0.y, b0.y);
            PACK_X2(bb[2], b0.z, b0.z);
            PACK_X2(bb[3], b0.w, b0.w);
            PACK_X2(bb[4], b1.x, b1.x);
            PACK_X2(bb[5], b1.y, b1.y);
            PACK_X2(bb[6], b1.z, b1.z);
            PACK_X2(bb[7], b1.w, b1.w);
#pragma unroll
            for (int p = 0; p < 2; p++)
#pragma unroll
                for (int j = 0; j < 8; j++)
                    FMA_X2I(acc2[p][j], aa[p], bb[j]);
        }
        __syncthreads();
    }

    // ---- fused epilogue: deg*bias, leaky, gate, sigmoid, blend, store ----
    float4 bias0 = *reinterpret_cast<const float4*>(&Wb[tx * 4]);
    float4 bias1 = *reinterpret_cast<const float4*>(&Wb[128 + tx * 4]);
    float4 gwx0  = *reinterpret_cast<const float4*>(&GW[tx * 4]);
    float4 gwx1  = *reinterpret_cast<const float4*>(&GW[128 + tx * 4]);
    float4 gwh0  = *reinterpret_cast<const float4*>(&GW[FF + tx * 4]);
    float4 gwh1  = *reinterpret_cast<const float4*>(&GW[FF + 128 + tx * 4]);
    const float gb = GB[0];
    const float bias[8] = {bias0.x, bias0.y, bias0.z, bias0.w,
                           bias1.x, bias1.y, bias1.z, bias1.w};
    const float gwh[8]  = {gwh0.x, gwh0.y, gwh0.z, gwh0.w,
                           gwh1.x, gwh1.y, gwh1.z, gwh1.w};
    const float gwx[8]  = {gwx0.x, gwx0.y, gwx0.z, gwx0.w,
                           gwx1.x, gwx1.y, gwx1.z, gwx1.w};

#pragma unroll
    for (int p = 0; p < 2; p++) {
        float rlo[8], rhi[8];
#pragma unroll
        for (int j = 0; j < 8; j++) UNPK_X2(rlo[j], rhi[j], acc2[p][j]);

#pragma unroll
        for (int s = 0; s < 2; s++) {
            const int m = m0 + ty * 4 + p * 2 + s;
            const float dg = DEG[m];
            float* rr = s ? rhi : rlo;

            float hp[8];
#pragma unroll
            for (int j = 0; j < 8; j++) {
                float v = rr[j] + dg * bias[j];
                hp[j] = (v > 0.0f) ? v : 0.2f * v;
            }

            const float* xr = X + (size_t)m * FF;
            float4 x0 = *reinterpret_cast<const float4*>(xr + tx * 4);
            float4 x1 = *reinterpret_cast<const float4*>(xr + 128 + tx * 4);
            float xv[8] = {x0.x, x0.y, x0.z, x0.w, x1.x, x1.y, x1.z, x1.w};

            float g = 0.0f;
#pragma unroll
            for (int j = 0; j < 8; j++)
                g += xv[j] * gwx[j] + hp[j] * gwh[j];
#pragma unroll
            for (int off = 16; off > 0; off >>= 1)
                g += __shfl_xor_sync(0xffffffffu, g, off);

            float coeff = 1.0f / (1.0f + expf(-(g + gb)));
            float om = 1.0f - coeff;

            float4 o0, o1;
            o0.x = coeff * xv[0] + om * hp[0];
            o0.y = coeff * xv[1] + om * hp[1];
            o0.z = coeff * xv[2] + om * hp[2];
            o0.w = coeff * xv[3] + om * hp[3];
            o1.x = coeff * xv[4] + om * hp[4];
            o1.y = coeff * xv[5] + om * hp[5];
            o1.z = coeff * xv[6] + om * hp[6];
            o1.w = coeff * xv[7] + om * hp[7];

            float* orow = OUT + (size_t)m * FF;
            *reinterpret_cast<float4*>(orow + tx * 4)       = o0;
            *reinterpret_cast<float4*>(orow + 128 + tx * 4) = o1;
        }
    }
}

// ---------------------------------------------------------------------------
extern "C" void kernel_launch(void* const* d_in, const int* in_sizes, int n_in,
                              void* d_out, int out_size)
{
    const float* x    = (const float*)d_in[0];   // [16,512,256]
    const float* adj  = (const float*)d_in[1];   // [16,512,512]
    const float* W_w  = (const float*)d_in[2];   // [256,256]
    const float* W_b  = (const float*)d_in[3];   // [256]
    // d_in[4] = A : dead code in the reference
    const float* gw   = (const float*)d_in[5];   // [1,512]
    const float* gb   = (const float*)d_in[6];   // [1]
    float* out = (float*)d_out;

    float* y;   cudaGetSymbolAddress((void**)&y,   g_y);
    float* deg; cudaGetSymbolAddress((void**)&deg, g_deg);

    const int smem1 = 2 * JT * FH * sizeof(float);   // 32 KB
    cudaFuncSetAttribute(agg_x_kernel,
                         cudaFuncAttributeMaxDynamicSharedMemorySize, smem1);
    dim3 grid1(NN / ICH, BB, 2);                 // 512 CTAs
    agg_x_kernel<<<grid1, 256, smem1>>>(x, adj, y, deg);

    gemm_fused_kernel<<<M_TOT / GBM, 256>>>(y, W_w, W_b, deg, x, gw, gb, out);
}

// round 11
// speedup vs baseline: 1.0656x; 1.0656x over previous
#include <cuda_runtime.h>
#include <cstdint>

// Problem shape (fixed by the dataset)
#define BB 16
#define NN 512
#define FF 256
#define M_TOT (BB * NN)   // 8192

typedef unsigned long long ull;

// Scratch
__device__ float g_y[M_TOT * FF];      // adj @ x
__device__ float g_deg[M_TOT];         // rowsum(adj)

// ---- packed f32x2 helpers ---------------------------------------------------
#define PACK_X2(d, lo, hi) \
    asm("mov.b64 %0, {%1, %2};" : "=l"(d) : "r"(__float_as_uint(lo)), "r"(__float_as_uint(hi)))
#define UNPK_X2(lo, hi, s) do { unsigned _l, _h; \
    asm("mov.b64 {%0, %1}, %2;" : "=r"(_l), "=r"(_h) : "l"(s)); \
    lo = __uint_as_float(_l); hi = __uint_as_float(_h); } while (0)
#define ADD_X2I(acc, a) \
    asm("add.rn.f32x2 %0, %0, %1;" : "+l"(acc) : "l"(a))
#define FMA_X2I(acc, a, b) \
    asm("fma.rn.f32x2 %0, %1, %2, %0;" : "+l"(acc) : "l"(a), "l"(b))

// ---- cp.async helpers -------------------------------------------------------
__device__ __forceinline__ void cp_async16(unsigned saddr, const void* gptr) {
    asm volatile("cp.async.cg.shared.global [%0], [%1], 16;"
                 :: "r"(saddr), "l"(gptr));
}
#define CP_COMMIT() asm volatile("cp.async.commit_group;")
#define CP_WAIT(n)  asm volatile("cp.async.wait_group %0;" :: "n"(n))

// ---------------------------------------------------------------------------
// Kernel 1: y[b,i,f] = sum_j adj[b,i,j] * x[b,j,f]   deg[b,i] = rowsum
// (round-9 version: cp.async x tiles + adj row prefetch, 19.8us measured)
// ---------------------------------------------------------------------------
#define ICH 32
#define JT  32
#define FH  128
#define TILE_F4 (JT * FH / 4)     // 1024 float4 per tile
#define NTILES  (NN / JT)         // 16

__global__ __launch_bounds__(256) void agg_x_kernel(
    const float* __restrict__ X,
    const float* __restrict__ ADJ,
    float* __restrict__ Y,
    float* __restrict__ DEG)
{
    extern __shared__ float xt[];   // 2 * JT*FH floats = 32 KB

    const int b    = blockIdx.y;
    const int i0   = blockIdx.x * ICH;
    const int fs   = blockIdx.z;
    const int t    = threadIdx.x;
    const int w    = t >> 5;
    const int lane = t & 31;

    const float4* xb4 = reinterpret_cast<const float4*>(X + (size_t)b * NN * FF + fs * FH);
    const unsigned sbase = (unsigned)__cvta_generic_to_shared(xt);

    ull acc2[4][2] = {{0ull,0ull},{0ull,0ull},{0ull,0ull},{0ull,0ull}};
    int degc[4] = {0, 0, 0, 0};

    const float* adj_base = ADJ + ((size_t)b * NN + i0 + w * 4) * NN + lane;

    auto issue = [&](int jt, int buf) {
#pragma unroll
        for (int p = 0; p < 4; p++) {
            int e   = t + p * 256;          // 0..1023
            int row = e >> 5;               // 0..31
            int c   = e & 31;               // float4 within row
            const float4* g = &xb4[(size_t)(jt * JT + row) * (FF / 4) + c];
            cp_async16(sbase + (unsigned)(buf * TILE_F4 + e) * 16u, g);
        }
        CP_COMMIT();
    };

    issue(0, 0);
    float av[4];
#pragma unroll
    for (int ii = 0; ii < 4; ii++)
        av[ii] = adj_base[(size_t)ii * NN];          // adj prefetch, tile 0

    for (int jt = 0; jt < NTILES; jt++) {
        const int buf = jt & 1;
        float avn[4] = {0.f, 0.f, 0.f, 0.f};
        if (jt + 1 < NTILES) {
            issue(jt + 1, buf ^ 1);
#pragma unroll
            for (int ii = 0; ii < 4; ii++)           // adj prefetch, next tile
                avn[ii] = adj_base[(size_t)ii * NN + (jt + 1) * JT];
            CP_WAIT(1);
        } else {
            CP_WAIT(0);
        }
        __syncthreads();

        unsigned m[4];
#pragma unroll
        for (int ii = 0; ii < 4; ii++) {
            m[ii] = __ballot_sync(0xffffffffu, av[ii] > 0.0f);
            degc[ii] += __popc(m[ii]);
        }

        const float* tb = xt + buf * (JT * FH) + lane * 4;
        while (m[0] | m[1] | m[2] | m[3]) {
#pragma unroll
            for (int ii = 0; ii < 4; ii++) {
                if (m[ii]) {
                    int j = __ffs(m[ii]) - 1;
                    m[ii] &= m[ii] - 1;
                    float4 h = *reinterpret_cast<const float4*>(tb + j * FH);
                    ull h01, h23;
                    PACK_X2(h01, h.x, h.y);
                    PACK_X2(h23, h.z, h.w);
                    ADD_X2I(acc2[ii][0], h01);
                    ADD_X2I(acc2[ii][1], h23);
                }
            }
        }
#pragma unroll
        for (int ii = 0; ii < 4; ii++) av[ii] = avn[ii];
        __syncthreads();
    }

#pragma unroll
    for (int ii = 0; ii < 4; ii++) {
        const int m_ = b * NN + i0 + w * 4 + ii;
        float4 o;
        UNPK_X2(o.x, o.y, acc2[ii][0]);
        UNPK_X2(o.z, o.w, acc2[ii][1]);
        *reinterpret_cast<float4*>(Y + (size_t)m_ * FF + fs * FH + lane * 4) = o;
        if (fs == 0 && lane == 0) DEG[m_] = (float)degc[ii];
    }
}

// ---------------------------------------------------------------------------
// Kernel 2: fully fused GEMM + gate + blend.   512 threads, BM=64, BN=256.
// 16 warps: warp wid owns rows m0+wid*4..+3; lane tx owns cols
// {tx*4..+3, 128+tx*4..+3}. Reg-prefetch double buffering, FFMA2 inner.
// acc = 4 rows x 8 cols = 16 ull -> ~100 regs -> 16 warps resident per SM.
// ---------------------------------------------------------------------------
#define GBM 64
#define GBK 16

__global__ __launch_bounds__(512, 1) void gemm_fused_kernel(
    const float* __restrict__ Y,
    const float* __restrict__ W,
    const float* __restrict__ Wb,
    const float* __restrict__ DEG,
    const float* __restrict__ X,
    const float* __restrict__ GW,
    const float* __restrict__ GB,
    float* __restrict__ OUT)
{
    __shared__ float As[GBK][GBM];     // 4 KB
    __shared__ float Bs[GBK][FF];      // 16 KB

    const int t   = threadIdx.x;
    const int tx  = t & 31;            // lane
    const int wid = t >> 5;            // warp 0..15
    const int m0  = blockIdx.x * GBM;

    const float4* Y4 = reinterpret_cast<const float4*>(Y);
    const float4* W4 = reinterpret_cast<const float4*>(W);

    // A prefetch: 64 rows x 4 float4 = 256 -> threads 0..255, 1 each
    const int ar = t >> 2, ac = t & 3;

    float4 pa;
    float4 pb[2];

    auto loadT = [&](int kt4) {      // kt4 = kt/4
        if (t < 256) pa = Y4[(size_t)(m0 + ar) * (FF / 4) + kt4 + ac];
#pragma unroll
        for (int p = 0; p < 2; p++) {
            int e = t + p * 512;                       // 0..1023
            pb[p] = W4[(size_t)(e >> 2) * (FF / 4) + kt4 + (e & 3)];
        }
    };
    auto storeT = [&]() {
        if (t < 256) {
            As[ac * 4 + 0][ar] = pa.x;
            As[ac * 4 + 1][ar] = pa.y;
            As[ac * 4 + 2][ar] = pa.z;
            As[ac * 4 + 3][ar] = pa.w;
        }
#pragma unroll
        for (int p = 0; p < 2; p++) {
            int e = t + p * 512;
            int n = e >> 2, c = e & 3;
            Bs[c * 4 + 0][n] = pb[p].x;
            Bs[c * 4 + 1][n] = pb[p].y;
            Bs[c * 4 + 2][n] = pb[p].z;
            Bs[c * 4 + 3][n] = pb[p].w;
        }
    };

    ull acc2[2][8];
#pragma unroll
    for (int p = 0; p < 2; p++)
#pragma unroll
        for (int j = 0; j < 8; j++) acc2[p][j] = 0ull;

    loadT(0);
    for (int kt = 0; kt < FF / GBK; kt++) {
        storeT();
        __syncthreads();
        if (kt + 1 < FF / GBK) loadT((kt + 1) * (GBK / 4));   // overlaps compute

#pragma unroll
        for (int k = 0; k < GBK; k++) {
            float4 a  = *reinterpret_cast<const float4*>(&As[k][wid * 4]);   // broadcast
            float4 b0 = *reinterpret_cast<const float4*>(&Bs[k][tx * 4]);
            float4 b1 = *reinterpret_cast<const float4*>(&Bs[k][128 + tx * 4]);
            ull aa[2], bb[8];
            PACK_X2(aa[0], a.x, a.y);
            PACK_X2(aa[1], a.z, a.w);
            PACK_X2(bb[0], b0.x, b0.x);
            PACK_X2(bb[1], b0.y, b0.y);
            PACK_X2(bb[2], b0.z, b0.z);
            PACK_X2(bb[3], b0.w, b0.w);
            PACK_X2(bb[4], b1.x, b1.x);
            PACK_X2(bb[5], b1.y, b1.y);
            PACK_X2(bb[6], b1.z, b1.z);
            PACK_X2(bb[7], b1.w, b1.w);
#pragma unroll
            for (int p = 0; p < 2; p++)
#pragma unroll
                for (int j = 0; j < 8; j++)
                    FMA_X2I(acc2[p][j], aa[p], bb[j]);
        }
        __syncthreads();
    }

    // ---- fused epilogue: deg*bias, leaky, gate, sigmoid, blend, store ----
    float4 bias0 = *reinterpret_cast<const float4*>(&Wb[tx * 4]);
    float4 bias1 = *reinterpret_cast<const float4*>(&Wb[128 + tx * 4]);
    float4 gwx0  = *reinterpret_cast<const float4*>(&GW[tx * 4]);
    float4 gwx1  = *reinterpret_cast<const float4*>(&GW[128 + tx * 4]);
    float4 gwh0  = *reinterpret_cast<const float4*>(&GW[FF + tx * 4]);
    float4 gwh1  = *reinterpret_cast<const float4*>(&GW[FF + 128 + tx * 4]);
    const float gb = GB[0];
    const float bias[8] = {bias0.x, bias0.y, bias0.z, bias0.w,
                           bias1.x, bias1.y, bias1.z, bias1.w};
    const float gwh[8]  = {gwh0.x, gwh0.y, gwh0.z, gwh0.w,
                           gwh1.x, gwh1.y, gwh1.z, gwh1.w};
    const float gwx[8]  = {gwx0.x, gwx0.y, gwx0.z, gwx0.w,
                           gwx1.x, gwx1.y, gwx1.z, gwx1.w};

#pragma unroll
    for (int p = 0; p < 2; p++) {
        float rlo[8], rhi[8];
#pragma unroll
        for (int j = 0; j < 8; j++) UNPK_X2(rlo[j], rhi[j], acc2[p][j]);

#pragma unroll
        for (int s = 0; s < 2; s++) {
            const int m = m0 + wid * 4 + p * 2 + s;
            const float dg = DEG[m];
            float* rr = s ? rhi : rlo;

            float hp[8];
#pragma unroll
            for (int j = 0; j < 8; j++) {
                float v = rr[j] + dg * bias[j];
                hp[j] = (v > 0.0f) ? v : 0.2f * v;
            }

            const float* xr = X + (size_t)m * FF;
            float4 x0 = *reinterpret_cast<const float4*>(xr + tx * 4);
            float4 x1 = *reinterpret_cast<const float4*>(xr + 128 + tx * 4);
            float xv[8] = {x0.x, x0.y, x0.z, x0.w, x1.x, x1.y, x1.z, x1.w};

            float g = 0.0f;
#pragma unroll
            for (int j = 0; j < 8; j++)
                g += xv[j] * gwx[j] + hp[j] * gwh[j];
#pragma unroll
            for (int off = 16; off > 0; off >>= 1)
                g += __shfl_xor_sync(0xffffffffu, g, off);

            float coeff = 1.0f / (1.0f + expf(-(g + gb)));
            float om = 1.0f - coeff;

            float4 o0, o1;
            o0.x = coeff * xv[0] + om * hp[0];
            o0.y = coeff * xv[1] + om * hp[1];
            o0.z = coeff * xv[2] + om * hp[2];
            o0.w = coeff * xv[3] + om * hp[3];
            o1.x = coeff * xv[4] + om * hp[4];
            o1.y = coeff * xv[5] + om * hp[5];
            o1.z = coeff * xv[6] + om * hp[6];
            o1.w = coeff * xv[7] + om * hp[7];

            float* orow = OUT + (size_t)m * FF;
            *reinterpret_cast<float4*>(orow + tx * 4)       = o0;
            *reinterpret_cast<float4*>(orow + 128 + tx * 4) = o1;
        }
    }
}

// ---------------------------------------------------------------------------
extern "C" void kernel_launch(void* const* d_in, const int* in_sizes, int n_in,
                              void* d_out, int out_size)
{
    const float* x    = (const float*)d_in[0];   // [16,512,256]
    const float* adj  = (const float*)d_in[1];   // [16,512,512]
    const float* W_w  = (const float*)d_in[2];   // [256,256]
    const float* W_b  = (const float*)d_in[3];   // [256]
    // d_in[4] = A : dead code in the reference
    const float* gw   = (const float*)d_in[5];   // [1,512]
    const float* gb   = (const float*)d_in[6];   // [1]
    float* out = (float*)d_out;

    float* y;   cudaGetSymbolAddress((void**)&y,   g_y);
    float* deg; cudaGetSymbolAddress((void**)&deg, g_deg);

    const int smem1 = 2 * JT * FH * sizeof(float);   // 32 KB
    cudaFuncSetAttribute(agg_x_kernel,
                         cudaFuncAttributeMaxDynamicSharedMemorySize, smem1);
    dim3 grid1(NN / ICH, BB, 2);                 // 512 CTAs
    agg_x_kernel<<<grid1, 256, smem1>>>(x, adj, y, deg);

    gemm_fused_kernel<<<M_TOT / GBM, 512>>>(y, W_w, W_b, deg, x, gw, gb, out);
}

// round 15
// speedup vs baseline: 1.4386x; 1.3501x over previous
#include <cuda_runtime.h>
#include <cuda_bf16.h>
#include <cstdint>

// Problem shape (fixed by the dataset)
#define BB 16
#define NN 512
#define FF 256
#define M_TOT (BB * NN)   // 8192

typedef unsigned long long ull;

// Scratch: bf16 hi/lo split of y = adj@x and of W; deg = rowsum(adj)
__device__ __nv_bfloat16 g_yh[M_TOT * FF];
__device__ __nv_bfloat16 g_yl[M_TOT * FF];
__device__ __nv_bfloat16 g_wh[FF * FF];
__device__ __nv_bfloat16 g_wl[FF * FF];
__device__ float g_deg[M_TOT];

// ---- packed f32x2 helpers ---------------------------------------------------
#define PACK_X2(d, lo, hi) \
    asm("mov.b64 %0, {%1, %2};" : "=l"(d) : "r"(__float_as_uint(lo)), "r"(__float_as_uint(hi)))
#define UNPK_X2(lo, hi, s) do { unsigned _l, _h; \
    asm("mov.b64 {%0, %1}, %2;" : "=r"(_l), "=r"(_h) : "l"(s)); \
    lo = __uint_as_float(_l); hi = __uint_as_float(_h); } while (0)
#define ADD_X2I(acc, a) \
    asm("add.rn.f32x2 %0, %0, %1;" : "+l"(acc) : "l"(a))

// ---- cp.async helpers -------------------------------------------------------
__device__ __forceinline__ void cp_async16(unsigned saddr, const void* gptr) {
    asm volatile("cp.async.cg.shared.global [%0], [%1], 16;"
                 :: "r"(saddr), "l"(gptr));
}
#define CP_COMMIT() asm volatile("cp.async.commit_group;")
#define CP_WAIT(n)  asm volatile("cp.async.wait_group %0;" :: "n"(n))

__device__ __forceinline__ unsigned smem_u32(const void* p) {
    return (unsigned)__cvta_generic_to_shared(p);
}

// ---- mma.sync / ldmatrix (standard PTX, works on plain sm_103) -------------
__device__ __forceinline__ void ldsm_x4(unsigned* r, unsigned addr) {
    asm volatile("ldmatrix.sync.aligned.m8n8.x4.shared.b16 {%0,%1,%2,%3}, [%4];"
                 : "=r"(r[0]), "=r"(r[1]), "=r"(r[2]), "=r"(r[3]) : "r"(addr));
}
__device__ __forceinline__ void mma16816(float* d, const unsigned* a, const unsigned* b) {
    asm volatile("mma.sync.aligned.m16n8k16.row.col.f32.bf16.bf16.f32 "
                 "{%0,%1,%2,%3}, {%4,%5,%6,%7}, {%8,%9}, {%0,%1,%2,%3};"
                 : "+f"(d[0]), "+f"(d[1]), "+f"(d[2]), "+f"(d[3])
                 : "r"(a[0]), "r"(a[1]), "r"(a[2]), "r"(a[3]), "r"(b[0]), "r"(b[1]));
}

__device__ __forceinline__ void bf16_split(float v, __nv_bfloat16& h, __nv_bfloat16& l) {
    h = __float2bfloat16(v);
    l = __float2bfloat16(v - __bfloat162float(h));
}

// ---------------------------------------------------------------------------
// Kernel 0: split W into bf16 hi/lo. 64 CTAs x 256 thr x 4 elements.
// ---------------------------------------------------------------------------
__global__ __launch_bounds__(256) void prep_w_kernel(const float* __restrict__ W) {
    int idx = blockIdx.x * 256 + threadIdx.x;          // float4 index, 16384 total
    float4 w = reinterpret_cast<const float4*>(W)[idx];
    __nv_bfloat16 h[4], l[4];
    bf16_split(w.x, h[0], l[0]);
    bf16_split(w.y, h[1], l[1]);
    bf16_split(w.z, h[2], l[2]);
    bf16_split(w.w, h[3], l[3]);
    *reinterpret_cast<uint2*>(&g_wh[idx * 4]) = *reinterpret_cast<uint2*>(h);
    *reinterpret_cast<uint2*>(&g_wl[idx * 4]) = *reinterpret_cast<uint2*>(l);
}

// ---------------------------------------------------------------------------
// Kernel 1: y[b,i,f] = sum_j adj[b,i,j]*x[b,j,f]; emits y as bf16 hi/lo + deg.
// (round-9 proven structure: cp.async x tiles + adj prefetch + 4-row drain)
// ---------------------------------------------------------------------------
#define ICH 32
#define JT  32
#define FH  128
#define TILE_F4 (JT * FH / 4)
#define NTILES  (NN / JT)

__global__ __launch_bounds__(256) void agg_x_kernel(
    const float* __restrict__ X,
    const float* __restrict__ ADJ,
    float* __restrict__ DEG)
{
    extern __shared__ float xt[];   // 32 KB

    const int b    = blockIdx.y;
    const int i0   = blockIdx.x * ICH;
    const int fs   = blockIdx.z;
    const int t    = threadIdx.x;
    const int w    = t >> 5;
    const int lane = t & 31;

    const float4* xb4 = reinterpret_cast<const float4*>(X + (size_t)b * NN * FF + fs * FH);
    const unsigned sbase = smem_u32(xt);

    ull acc2[4][2] = {{0ull,0ull},{0ull,0ull},{0ull,0ull},{0ull,0ull}};
    int degc[4] = {0, 0, 0, 0};

    const float* adj_base = ADJ + ((size_t)b * NN + i0 + w * 4) * NN + lane;

    auto issue = [&](int jt, int buf) {
#pragma unroll
        for (int p = 0; p < 4; p++) {
            int e   = t + p * 256;
            int row = e >> 5;
            int c   = e & 31;
            cp_async16(sbase + (unsigned)(buf * TILE_F4 + e) * 16u,
                       &xb4[(size_t)(jt * JT + row) * (FF / 4) + c]);
        }
        CP_COMMIT();
    };

    issue(0, 0);
    float av[4];
#pragma unroll
    for (int ii = 0; ii < 4; ii++) av[ii] = adj_base[(size_t)ii * NN];

    for (int jt = 0; jt < NTILES; jt++) {
        const int buf = jt & 1;
        float avn[4] = {0.f, 0.f, 0.f, 0.f};
        if (jt + 1 < NTILES) {
            issue(jt + 1, buf ^ 1);
#pragma unroll
            for (int ii = 0; ii < 4; ii++)
                avn[ii] = adj_base[(size_t)ii * NN + (jt + 1) * JT];
            CP_WAIT(1);
        } else {
            CP_WAIT(0);
        }
        __syncthreads();

        unsigned m[4];
#pragma unroll
        for (int ii = 0; ii < 4; ii++) {
            m[ii] = __ballot_sync(0xffffffffu, av[ii] > 0.0f);
            degc[ii] += __popc(m[ii]);
        }

        const float* tb = xt + buf * (JT * FH) + lane * 4;
        while (m[0] | m[1] | m[2] | m[3]) {
#pragma unroll
            for (int ii = 0; ii < 4; ii++) {
                if (m[ii]) {
                    int j = __ffs(m[ii]) - 1;
                    m[ii] &= m[ii] - 1;
                    float4 h = *reinterpret_cast<const float4*>(tb + j * FH);
                    ull h01, h23;
                    PACK_X2(h01, h.x, h.y);
                    PACK_X2(h23, h.z, h.w);
                    ADD_X2I(acc2[ii][0], h01);
                    ADD_X2I(acc2[ii][1], h23);
                }
            }
        }
#pragma unroll
        for (int ii = 0; ii < 4; ii++) av[ii] = avn[ii];
        __syncthreads();
    }

#pragma unroll
    for (int ii = 0; ii < 4; ii++) {
        const int m_ = b * NN + i0 + w * 4 + ii;
        float o[4];
        UNPK_X2(o[0], o[1], acc2[ii][0]);
        UNPK_X2(o[2], o[3], acc2[ii][1]);
        __nv_bfloat16 hh[4], ll[4];
#pragma unroll
        for (int q = 0; q < 4; q++) bf16_split(o[q], hh[q], ll[q]);
        const size_t off = (size_t)m_ * FF + fs * FH + lane * 4;
        *reinterpret_cast<uint2*>(&g_yh[off]) = *reinterpret_cast<uint2*>(hh);
        *reinterpret_cast<uint2*>(&g_yl[off]) = *reinterpret_cast<uint2*>(ll);
        if (fs == 0 && lane == 0) DEG[m_] = (float)degc[ii];
    }
}

// ---------------------------------------------------------------------------
// Kernel 2: HMMA (mma.sync bf16) GEMM, K=768 logical (yh.wh + yh.wl + yl.wh),
// fused gate + blend. 128 CTAs x 512 threads. BM=64, BN=256.
// Warp grid 2(M) x 8(N): warp tile 32x32 = acc[2][4][4].
// K staged in 6 chunks of 128 via double-buffered cp.async; smem rows padded
// to 272B so ldmatrix.x4 is bank-conflict-free.
// ---------------------------------------------------------------------------
#define STRB   272                       // padded row stride in bytes (136 bf16)
#define ABUF   17408                     // 64 * 272
#define BBUF   69632                     // 256 * 272
#define OFF_A  0
#define OFF_B  (2 * ABUF)                // 34816
#define OFF_GATEP (OFF_B + 2 * BBUF)     // 174080, 8*64 floats
#define OFF_COEFF (OFF_GATEP + 2048)     // 176128, 64 floats
#define SMEM_TOT  (OFF_COEFF + 256)      // 176384

__global__ __launch_bounds__(512, 1) void gemm_mma_kernel(
    const float* __restrict__ Wb,
    const float* __restrict__ DEG,
    const float* __restrict__ X,
    const float* __restrict__ GW,
    const float* __restrict__ GB,
    float* __restrict__ OUT)
{
    extern __shared__ char smem[];
    const unsigned sb = smem_u32(smem);
    const int t    = threadIdx.x;
    const int lane = t & 31;
    const int wid  = t >> 5;             // 0..15
    const int wm   = wid >> 3;           // 0..1  (M warp)
    const int wn   = wid & 7;            // 0..7  (N warp)
    const int m0   = blockIdx.x * 64;

    // stage chunk c (0..5) into buffer buf. seg = c/2 selects hi/lo product.
    auto issue = [&](int c, int buf) {
        const int seg  = c >> 1;
        const int koff = (c & 1) * 128;
        const __nv_bfloat16* As = (seg < 2) ? g_yh : g_yl;
        const __nv_bfloat16* Bs = (seg == 1) ? g_wl : g_wh;
#pragma unroll
        for (int p = 0; p < 2; p++) {                 // A: 64 rows x 16 units
            int e = t + p * 512;                      // 0..1023
            int row = e >> 4, u = e & 15;
            cp_async16(sb + OFF_A + buf * ABUF + row * STRB + u * 16,
                       &As[(size_t)(m0 + row) * FF + koff + u * 8]);
        }
#pragma unroll
        for (int p = 0; p < 8; p++) {                 // B: 256 rows x 16 units
            int e = t + p * 512;                      // 0..4095
            int row = e >> 4, u = e & 15;
            cp_async16(sb + OFF_B + buf * BBUF + row * STRB + u * 16,
                       &Bs[(size_t)row * FF + koff + u * 8]);
        }
        CP_COMMIT();
    };

    float acc[2][4][4];
#pragma unroll
    for (int mf = 0; mf < 2; mf++)
#pragma unroll
        for (int nf = 0; nf < 4; nf++)
#pragma unroll
            for (int q = 0; q < 4; q++) acc[mf][nf][q] = 0.0f;

    issue(0, 0);
    for (int c = 0; c < 6; c++) {
        const int buf = c & 1;
        if (c + 1 < 6) {
            issue(c + 1, buf ^ 1);
            CP_WAIT(1);
        } else {
            CP_WAIT(0);
        }
        __syncthreads();

        const unsigned aBase = sb + OFF_A + buf * ABUF;
        const unsigned bBase = sb + OFF_B + buf * BBUF;

#pragma unroll
        for (int ks = 0; ks < 8; ks++) {
            const int k0 = ks * 16;
            unsigned a[2][4], b[2][4];
#pragma unroll
            for (int mf = 0; mf < 2; mf++) {
                unsigned addr = aBase
                    + (unsigned)(wm * 32 + mf * 16 + (lane & 15)) * STRB
                    + (unsigned)(k0 + (lane >> 4) * 8) * 2;
                ldsm_x4(a[mf], addr);
            }
#pragma unroll
            for (int nf2 = 0; nf2 < 2; nf2++) {
                unsigned row = (unsigned)(wn * 32 + nf2 * 16
                                          + ((lane >> 4) & 1) * 8 + (lane & 7));
                unsigned kk  = (unsigned)(k0 + ((lane >> 3) & 1) * 8);
                ldsm_x4(b[nf2], bBase + row * STRB + kk * 2);
            }
#pragma unroll
            for (int mf = 0; mf < 2; mf++)
#pragma unroll
                for (int nf = 0; nf < 4; nf++)
                    mma16816(acc[mf][nf], a[mf], &b[nf >> 1][(nf & 1) * 2]);
        }
        __syncthreads();   // all warps done with buf before it is re-filled
    }

    // ---- fused epilogue ----
    const int qr = lane >> 2;            // 0..7 row in frag
    const int qc = (lane & 3) * 2;       // col pair
    float* gatep   = (float*)(smem + OFF_GATEP);   // [8][64]
    float* coeff_s = (float*)(smem + OFF_COEFF);   // [64]

    float2 bias2[4], gh2[4], gx2[4];
#pragma unroll
    for (int nf = 0; nf < 4; nf++) {
        const int n = wn * 32 + nf * 8 + qc;
        bias2[nf] = *reinterpret_cast<const float2*>(&Wb[n]);
        gh2[nf]   = *reinterpret_cast<const float2*>(&GW[FF + n]);
        gx2[nf]   = *reinterpret_cast<const float2*>(&GW[n]);
    }

    float2 xv[2][2][4];
    float gp[2][2] = {{0.f, 0.f}, {0.f, 0.f}};
#pragma unroll
    for (int mf = 0; mf < 2; mf++)
#pragma unroll
        for (int h = 0; h < 2; h++) {
            const int row = wm * 32 + mf * 16 + h * 8 + qr;
            const int m   = m0 + row;
            const float dg = DEG[m];
#pragma unroll
            for (int nf = 0; nf < 4; nf++) {
                const int n = wn * 32 + nf * 8 + qc;
                float v0 = acc[mf][nf][h * 2]     + dg * bias2[nf].x;
                float v1 = acc[mf][nf][h * 2 + 1] + dg * bias2[nf].y;
                v0 = (v0 > 0.0f) ? v0 : 0.2f * v0;
                v1 = (v1 > 0.0f) ? v1 : 0.2f * v1;
                acc[mf][nf][h * 2]     = v0;      // now hp
                acc[mf][nf][h * 2 + 1] = v1;
                float2 x2 = *reinterpret_cast<const float2*>(&X[(size_t)m * FF + n]);
                xv[mf][h][nf] = x2;
                gp[mf][h] += v0 * gh2[nf].x + v1 * gh2[nf].y
                           + x2.x * gx2[nf].x + x2.y * gx2[nf].y;
            }
        }

    // quad reduce (lanes sharing a row)
#pragma unroll
    for (int mf = 0; mf < 2; mf++)
#pragma unroll
        for (int h = 0; h < 2; h++) {
            gp[mf][h] += __shfl_xor_sync(0xffffffffu, gp[mf][h], 1);
            gp[mf][h] += __shfl_xor_sync(0xffffffffu, gp[mf][h], 2);
        }
    if ((lane & 3) == 0) {
#pragma unroll
        for (int mf = 0; mf < 2; mf++)
#pragma unroll
            for (int h = 0; h < 2; h++)
                gatep[wn * 64 + wm * 32 + mf * 16 + h * 8 + qr] = gp[mf][h];
    }
    __syncthreads();

    if (t < 64) {
        float s = GB[0];
#pragma unroll
        for (int i = 0; i < 8; i++) s += gatep[i * 64 + t];
        coeff_s[t] = 1.0f / (1.0f + expf(-s));
    }
    __syncthreads();

#pragma unroll
    for (int mf = 0; mf < 2; mf++)
#pragma unroll
        for (int h = 0; h < 2; h++) {
            const int row = wm * 32 + mf * 16 + h * 8 + qr;
            const int m   = m0 + row;
            const float cf = coeff_s[row];
            const float om = 1.0f - cf;
#pragma unroll
            for (int nf = 0; nf < 4; nf++) {
                const int n = wn * 32 + nf * 8 + qc;
                float2 o;
                o.x = cf * xv[mf][h][nf].x + om * acc[mf][nf][h * 2];
                o.y = cf * xv[mf][h][nf].y + om * acc[mf][nf][h * 2 + 1];
                *reinterpret_cast<float2*>(&OUT[(size_t)m * FF + n]) = o;
            }
        }
}

// ---------------------------------------------------------------------------
extern "C" void kernel_launch(void* const* d_in, const int* in_sizes, int n_in,
                              void* d_out, int out_size)
{
    const float* x    = (const float*)d_in[0];   // [16,512,256]
    const float* adj  = (const float*)d_in[1];   // [16,512,512]
    const float* W_w  = (const float*)d_in[2];   // [256,256]
    const float* W_b  = (const float*)d_in[3];   // [256]
    // d_in[4] = A : dead code in the reference
    const float* gw   = (const float*)d_in[5];   // [1,512]
    const float* gb   = (const float*)d_in[6];   // [1]
    float* out = (float*)d_out;

    float* deg; cudaGetSymbolAddress((void**)&deg, g_deg);

    prep_w_kernel<<<64, 256>>>(W_w);

    const int smem1 = 2 * JT * FH * sizeof(float);   // 32 KB
    cudaFuncSetAttribute(agg_x_kernel,
                         cudaFuncAttributeMaxDynamicSharedMemorySize, smem1);
    dim3 grid1(NN / ICH, BB, 2);                     // 512 CTAs
    agg_x_kernel<<<grid1, 256, smem1>>>(x, adj, deg);

    cudaFuncSetAttribute(gemm_mma_kernel,
                         cudaFuncAttributeMaxDynamicSharedMemorySize, SMEM_TOT);
    gemm_mma_kernel<<<M_TOT / 64, 512, SMEM_TOT>>>(W_b, deg, x, gw, gb, out);
}

// round 16
// speedup vs baseline: 1.4487x; 1.0070x over previous
#include <cuda_runtime.h>
#include <cuda_fp16.h>
#include <cstdint>

// Problem shape (fixed by the dataset)
#define BB 16
#define NN 512
#define FF 256
#define M_TOT (BB * NN)   // 8192

typedef unsigned long long ull;

// Scratch: fp16 hi/lo split of y = adj@x, fp16 W; deg = rowsum(adj)
__device__ __half g_yh[M_TOT * FF];
__device__ __half g_yl[M_TOT * FF];
__device__ __half g_wh[FF * FF];
__device__ float  g_deg[M_TOT];

// ---- packed f32x2 helpers ---------------------------------------------------
#define PACK_X2(d, lo, hi) \
    asm("mov.b64 %0, {%1, %2};" : "=l"(d) : "r"(__float_as_uint(lo)), "r"(__float_as_uint(hi)))
#define UNPK_X2(lo, hi, s) do { unsigned _l, _h; \
    asm("mov.b64 {%0, %1}, %2;" : "=r"(_l), "=r"(_h) : "l"(s)); \
    lo = __uint_as_float(_l); hi = __uint_as_float(_h); } while (0)
#define ADD_X2I(acc, a) \
    asm("add.rn.f32x2 %0, %0, %1;" : "+l"(acc) : "l"(a))

// ---- cp.async helpers -------------------------------------------------------
__device__ __forceinline__ void cp_async16(unsigned saddr, const void* gptr) {
    asm volatile("cp.async.cg.shared.global [%0], [%1], 16;"
                 :: "r"(saddr), "l"(gptr));
}
#define CP_COMMIT() asm volatile("cp.async.commit_group;")
#define CP_WAIT(n)  asm volatile("cp.async.wait_group %0;" :: "n"(n))

__device__ __forceinline__ unsigned smem_u32(const void* p) {
    return (unsigned)__cvta_generic_to_shared(p);
}

// ---- mma.sync / ldmatrix (standard PTX, works on plain sm_103) -------------
__device__ __forceinline__ void ldsm_x4(unsigned* r, unsigned addr) {
    asm volatile("ldmatrix.sync.aligned.m8n8.x4.shared.b16 {%0,%1,%2,%3}, [%4];"
                 : "=r"(r[0]), "=r"(r[1]), "=r"(r[2]), "=r"(r[3]) : "r"(addr));
}
__device__ __forceinline__ void mma16816(float* d, const unsigned* a, const unsigned* b) {
    asm volatile("mma.sync.aligned.m16n8k16.row.col.f32.f16.f16.f32 "
                 "{%0,%1,%2,%3}, {%4,%5,%6,%7}, {%8,%9}, {%0,%1,%2,%3};"
                 : "+f"(d[0]), "+f"(d[1]), "+f"(d[2]), "+f"(d[3])
                 : "r"(a[0]), "r"(a[1]), "r"(a[2]), "r"(a[3]), "r"(b[0]), "r"(b[1]));
}

__device__ __forceinline__ void f16_split(float v, __half& h, __half& l) {
    h = __float2half(v);
    l = __float2half(v - __half2float(h));
}

// ---------------------------------------------------------------------------
// Kernel 1: y[b,i,f] = sum_j adj[b,i,j]*x[b,j,f]; emits y as fp16 hi/lo + deg.
// ICH=64: warp owns 8 i-rows (8-way interleaved drain), lane owns 4 features.
// First 16384 global threads also convert W -> fp16 (folds old prep_w launch).
// ---------------------------------------------------------------------------
#define ICH 64
#define JT  32
#define FH  128
#define TILE_F4 (JT * FH / 4)
#define NTILES  (NN / JT)

__global__ __launch_bounds__(256) void agg_x_kernel(
    const float* __restrict__ X,
    const float* __restrict__ ADJ,
    const float* __restrict__ W,
    float* __restrict__ DEG)
{
    extern __shared__ float xt[];   // 32 KB

    const int b    = blockIdx.y;
    const int i0   = blockIdx.x * ICH;
    const int fs   = blockIdx.z;
    const int t    = threadIdx.x;
    const int w    = t >> 5;
    const int lane = t & 31;

    // ---- folded W -> fp16 conversion (one float4 per thread, 16384 total) ----
    {
        const int gid = (blockIdx.x + (blockIdx.y << 3) + (blockIdx.z << 7)) * 256 + t;
        if (gid < (FF * FF / 4)) {
            float4 w4 = reinterpret_cast<const float4*>(W)[gid];
            __half h[4] = {__float2half(w4.x), __float2half(w4.y),
                           __float2half(w4.z), __float2half(w4.w)};
            *reinterpret_cast<uint2*>(&g_wh[gid * 4]) = *reinterpret_cast<uint2*>(h);
        }
    }

    const float4* xb4 = reinterpret_cast<const float4*>(X + (size_t)b * NN * FF + fs * FH);
    const unsigned sbase = smem_u32(xt);

    ull acc2[8][2];
    int degc[8];
#pragma unroll
    for (int ii = 0; ii < 8; ii++) {
        acc2[ii][0] = acc2[ii][1] = 0ull;
        degc[ii] = 0;
    }

    const float* adj_base = ADJ + ((size_t)b * NN + i0 + w * 8) * NN + lane;

    auto issue = [&](int jt, int buf) {
#pragma unroll
        for (int p = 0; p < 4; p++) {
            int e   = t + p * 256;
            int row = e >> 5;
            int c   = e & 31;
            cp_async16(sbase + (unsigned)(buf * TILE_F4 + e) * 16u,
                       &xb4[(size_t)(jt * JT + row) * (FF / 4) + c]);
        }
        CP_COMMIT();
    };

    issue(0, 0);
    float av[8];
#pragma unroll
    for (int ii = 0; ii < 8; ii++) av[ii] = adj_base[(size_t)ii * NN];

    for (int jt = 0; jt < NTILES; jt++) {
        const int buf = jt & 1;
        float avn[8] = {0.f, 0.f, 0.f, 0.f, 0.f, 0.f, 0.f, 0.f};
        if (jt + 1 < NTILES) {
            issue(jt + 1, buf ^ 1);
#pragma unroll
            for (int ii = 0; ii < 8; ii++)
                avn[ii] = adj_base[(size_t)ii * NN + (jt + 1) * JT];
            CP_WAIT(1);
        } else {
            CP_WAIT(0);
        }
        __syncthreads();

        unsigned m[8];
#pragma unroll
        for (int ii = 0; ii < 8; ii++) {
            m[ii] = __ballot_sync(0xffffffffu, av[ii] > 0.0f);
            degc[ii] += __popc(m[ii]);
        }

        const float* tb = xt + buf * (JT * FH) + lane * 4;
        while (m[0] | m[1] | m[2] | m[3] | m[4] | m[5] | m[6] | m[7]) {
#pragma unroll
            for (int ii = 0; ii < 8; ii++) {
                if (m[ii]) {
                    int j = __ffs(m[ii]) - 1;
                    m[ii] &= m[ii] - 1;
                    float4 h = *reinterpret_cast<const float4*>(tb + j * FH);
                    ull h01, h23;
                    PACK_X2(h01, h.x, h.y);
                    PACK_X2(h23, h.z, h.w);
                    ADD_X2I(acc2[ii][0], h01);
                    ADD_X2I(acc2[ii][1], h23);
                }
            }
        }
#pragma unroll
        for (int ii = 0; ii < 8; ii++) av[ii] = avn[ii];
        __syncthreads();
    }

#pragma unroll
    for (int ii = 0; ii < 8; ii++) {
        const int m_ = b * NN + i0 + w * 8 + ii;
        float o[4];
        UNPK_X2(o[0], o[1], acc2[ii][0]);
        UNPK_X2(o[2], o[3], acc2[ii][1]);
        __half hh[4], ll[4];
#pragma unroll
        for (int q = 0; q < 4; q++) f16_split(o[q], hh[q], ll[q]);
        const size_t off = (size_t)m_ * FF + fs * FH + lane * 4;
        *reinterpret_cast<uint2*>(&g_yh[off]) = *reinterpret_cast<uint2*>(hh);
        *reinterpret_cast<uint2*>(&g_yl[off]) = *reinterpret_cast<uint2*>(ll);
        if (fs == 0 && lane == 0) DEG[m_] = (float)degc[ii];
    }
}

// ---------------------------------------------------------------------------
// Kernel 2: HMMA fp16 GEMM, K=512 logical (yh.wh + yl.wh = y.wh),
// fused gate + blend. 128 CTAs x 512 threads. BM=64, BN=256.
// B (wh, full 256x256 fp16) staged ONCE resident in smem (stride 528B,
// conflict-free); A staged in 4 chunks of 128 via double-buffered cp.async.
// ---------------------------------------------------------------------------
#define ASTR   272                       // A row stride bytes (128 fp16 + pad)
#define BSTR   528                       // B row stride bytes (256 fp16 + pad)
#define ABUF   (64 * ASTR)               // 17408
#define OFF_A  0
#define OFF_B  (2 * ABUF)                // 34816
#define OFF_GATEP (OFF_B + 256 * BSTR)   // 169984, 8*64 floats
#define OFF_COEFF (OFF_GATEP + 2048)     // 172032, 64 floats
#define SMEM_TOT  (OFF_COEFF + 256)      // 172288

__global__ __launch_bounds__(512, 1) void gemm_mma_kernel(
    const float* __restrict__ Wb,
    const float* __restrict__ DEG,
    const float* __restrict__ X,
    const float* __restrict__ GW,
    const float* __restrict__ GB,
    float* __restrict__ OUT)
{
    extern __shared__ char smem[];
    const unsigned sb = smem_u32(smem);
    const int t    = threadIdx.x;
    const int lane = t & 31;
    const int wid  = t >> 5;             // 0..15
    const int wm   = wid >> 3;           // 0..1  (M warp)
    const int wn   = wid & 7;            // 0..7  (N warp)
    const int m0   = blockIdx.x * 64;

    // ---- stage B once: wh full [256 rows x 256 cols] fp16 ----
#pragma unroll
    for (int p = 0; p < 16; p++) {
        int e   = t + p * 512;           // 0..8191
        int row = e >> 5, u = e & 31;
        cp_async16(sb + OFF_B + row * BSTR + u * 16,
                   &g_wh[(size_t)row * FF + u * 8]);
    }
    CP_COMMIT();

    // stage A chunk c (0..3) into buffer buf
    auto issueA = [&](int c, int buf) {
        const __half* As = (c < 2) ? g_yh : g_yl;
        const int koff = (c & 1) * 128;
#pragma unroll
        for (int p = 0; p < 2; p++) {    // 64 rows x 8 units
            int e = t + p * 512;         // 0..1023
            int row = e >> 4, u = e & 15;
            cp_async16(sb + OFF_A + buf * ABUF + row * ASTR + u * 16,
                       &As[(size_t)(m0 + row) * FF + koff + u * 8]);
        }
        CP_COMMIT();
    };

    float acc[2][4][4];
#pragma unroll
    for (int mf = 0; mf < 2; mf++)
#pragma unroll
        for (int nf = 0; nf < 4; nf++)
#pragma unroll
            for (int q = 0; q < 4; q++) acc[mf][nf][q] = 0.0f;

    issueA(0, 0);
    for (int c = 0; c < 4; c++) {
        const int buf = c & 1;
        if (c + 1 < 4) {
            issueA(c + 1, buf ^ 1);
            CP_WAIT(1);                  // B + A(c) complete, A(c+1) pending
        } else {
            CP_WAIT(0);
        }
        __syncthreads();

        const unsigned aBase = sb + OFF_A + buf * ABUF;
        const unsigned bBase = sb + OFF_B;
        const int koff = (c & 1) * 128;

#pragma unroll
        for (int ks = 0; ks < 8; ks++) {
            const int k0 = ks * 16;
            unsigned a[2][4], b[2][4];
#pragma unroll
            for (int mf = 0; mf < 2; mf++) {
                unsigned addr = aBase
                    + (unsigned)(wm * 32 + mf * 16 + (lane & 15)) * ASTR
                    + (unsigned)(k0 + (lane >> 4) * 8) * 2;
                ldsm_x4(a[mf], addr);
            }
#pragma unroll
            for (int nf2 = 0; nf2 < 2; nf2++) {
                unsigned row = (unsigned)(wn * 32 + nf2 * 16
                                          + ((lane >> 4) & 1) * 8 + (lane & 7));
                unsigned kk  = (unsigned)(koff + k0 + ((lane >> 3) & 1) * 8);
                ldsm_x4(b[nf2], bBase + row * BSTR + kk * 2);
            }
#pragma unroll
            for (int mf = 0; mf < 2; mf++)
#pragma unroll
                for (int nf = 0; nf < 4; nf++)
                    mma16816(acc[mf][nf], a[mf], &b[nf >> 1][(nf & 1) * 2]);
        }
        __syncthreads();   // all warps done with A buf before it is re-filled
    }

    // ---- fused epilogue ----
    const int qr = lane >> 2;            // 0..7 row in frag
    const int qc = (lane & 3) * 2;       // col pair
    float* gatep   = (float*)(smem + OFF_GATEP);   // [8][64]
    float* coeff_s = (float*)(smem + OFF_COEFF);   // [64]

    float2 bias2[4], gh2[4], gx2[4];
#pragma unroll
    for (int nf = 0; nf < 4; nf++) {
        const int n = wn * 32 + nf * 8 + qc;
        bias2[nf] = *reinterpret_cast<const float2*>(&Wb[n]);
        gh2[nf]   = *reinterpret_cast<const float2*>(&GW[FF + n]);
        gx2[nf]   = *reinterpret_cast<const float2*>(&GW[n]);
    }

    float2 xv[2][2][4];
    float gp[2][2] = {{0.f, 0.f}, {0.f, 0.f}};
#pragma unroll
    for (int mf = 0; mf < 2; mf++)
#pragma unroll
        for (int h = 0; h < 2; h++) {
            const int row = wm * 32 + mf * 16 + h * 8 + qr;
            const int m   = m0 + row;
            const float dg = DEG[m];
#pragma unroll
            for (int nf = 0; nf < 4; nf++) {
                const int n = wn * 32 + nf * 8 + qc;
                float v0 = acc[mf][nf][h * 2]     + dg * bias2[nf].x;
                float v1 = acc[mf][nf][h * 2 + 1] + dg * bias2[nf].y;
                v0 = (v0 > 0.0f) ? v0 : 0.2f * v0;
                v1 = (v1 > 0.0f) ? v1 : 0.2f * v1;
                acc[mf][nf][h * 2]     = v0;      // now hp
                acc[mf][nf][h * 2 + 1] = v1;
                float2 x2 = *reinterpret_cast<const float2*>(&X[(size_t)m * FF + n]);
                xv[mf][h][nf] = x2;
                gp[mf][h] += v0 * gh2[nf].x + v1 * gh2[nf].y
                           + x2.x * gx2[nf].x + x2.y * gx2[nf].y;
            }
        }

    // quad reduce (lanes sharing a row)
#pragma unroll
    for (int mf = 0; mf < 2; mf++)
#pragma unroll
        for (int h = 0; h < 2; h++) {
            gp[mf][h] += __shfl_xor_sync(0xffffffffu, gp[mf][h], 1);
            gp[mf][h] += __shfl_xor_sync(0xffffffffu, gp[mf][h], 2);
        }
    if ((lane & 3) == 0) {
#pragma unroll
        for (int mf = 0; mf < 2; mf++)
#pragma unroll
            for (int h = 0; h < 2; h++)
                gatep[wn * 64 + wm * 32 + mf * 16 + h * 8 + qr] = gp[mf][h];
    }
    __syncthreads();

    if (t < 64) {
        float s = GB[0];
#pragma unroll
        for (int i = 0; i < 8; i++) s += gatep[i * 64 + t];
        coeff_s[t] = 1.0f / (1.0f + expf(-s));
    }
    __syncthreads();

#pragma unroll
    for (int mf = 0; mf < 2; mf++)
#pragma unroll
        for (int h = 0; h < 2; h++) {
            const int row = wm * 32 + mf * 16 + h * 8 + qr;
            const int m   = m0 + row;
            const float cf = coeff_s[row];
            const float om = 1.0f - cf;
#pragma unroll
            for (int nf = 0; nf < 4; nf++) {
                const int n = wn * 32 + nf * 8 + qc;
                float2 o;
                o.x = cf * xv[mf][h][nf].x + om * acc[mf][nf][h * 2];
                o.y = cf * xv[mf][h][nf].y + om * acc[mf][nf][h * 2 + 1];
                *reinterpret_cast<float2*>(&OUT[(size_t)m * FF + n]) = o;
            }
        }
}

// ---------------------------------------------------------------------------
extern "C" void kernel_launch(void* const* d_in, const int* in_sizes, int n_in,
                              void* d_out, int out_size)
{
    const float* x    = (const float*)d_in[0];   // [16,512,256]
    const float* adj  = (const float*)d_in[1];   // [16,512,512]
    const float* W_w  = (const float*)d_in[2];   // [256,256]
    const float* W_b  = (const float*)d_in[3];   // [256]
    // d_in[4] = A : dead code in the reference
    const float* gw   = (const float*)d_in[5];   // [1,512]
    const float* gb   = (const float*)d_in[6];   // [1]
    float* out = (float*)d_out;

    float* deg; cudaGetSymbolAddress((void**)&deg, g_deg);

    const int smem1 = 2 * JT * FH * sizeof(float);   // 32 KB
    cudaFuncSetAttribute(agg_x_kernel,
                         cudaFuncAttributeMaxDynamicSharedMemorySize, smem1);
    dim3 grid1(NN / ICH, BB, 2);                     // (8,16,2) = 256 CTAs
    agg_x_kernel<<<grid1, 256, smem1>>>(x, adj, W_w, deg);

    cudaFuncSetAttribute(gemm_mma_kernel,
                         cudaFuncAttributeMaxDynamicSharedMemorySize, SMEM_TOT);
    gemm_mma_kernel<<<M_TOT / 64, 512, SMEM_TOT>>>(W_b, deg, x, gw, gb, out);
}

// round 17
// speedup vs baseline: 1.5931x; 1.0996x over previous
#include <cuda_runtime.h>
#include <cuda_fp16.h>
#include <cstdint>

// Problem shape (fixed by the dataset)
#define BB 16
#define NN 512
#define FF 256
#define M_TOT (BB * NN)   // 8192

typedef unsigned long long ull;

// Scratch: fp16 hi/lo split of y = adj@x, fp16 W; deg = rowsum(adj)
__device__ __half g_yh[M_TOT * FF];
__device__ __half g_yl[M_TOT * FF];
__device__ __half g_wh[FF * FF];
__device__ float  g_deg[M_TOT];

// ---- packed f32x2 helpers ---------------------------------------------------
#define PACK_X2(d, lo, hi) \
    asm("mov.b64 %0, {%1, %2};" : "=l"(d) : "r"(__float_as_uint(lo)), "r"(__float_as_uint(hi)))
#define UNPK_X2(lo, hi, s) do { unsigned _l, _h; \
    asm("mov.b64 {%0, %1}, %2;" : "=r"(_l), "=r"(_h) : "l"(s)); \
    lo = __uint_as_float(_l); hi = __uint_as_float(_h); } while (0)
#define ADD_X2I(acc, a) \
    asm("add.rn.f32x2 %0, %0, %1;" : "+l"(acc) : "l"(a))

// ---- cp.async helpers -------------------------------------------------------
__device__ __forceinline__ void cp_async16(unsigned saddr, const void* gptr) {
    asm volatile("cp.async.cg.shared.global [%0], [%1], 16;"
                 :: "r"(saddr), "l"(gptr));
}
#define CP_COMMIT() asm volatile("cp.async.commit_group;")
#define CP_WAIT(n)  asm volatile("cp.async.wait_group %0;" :: "n"(n))

__device__ __forceinline__ unsigned smem_u32(const void* p) {
    return (unsigned)__cvta_generic_to_shared(p);
}

// ---- mma.sync / ldmatrix (standard PTX, works on plain sm_103) -------------
__device__ __forceinline__ void ldsm_x4(unsigned* r, unsigned addr) {
    asm volatile("ldmatrix.sync.aligned.m8n8.x4.shared.b16 {%0,%1,%2,%3}, [%4];"
                 : "=r"(r[0]), "=r"(r[1]), "=r"(r[2]), "=r"(r[3]) : "r"(addr));
}
__device__ __forceinline__ void mma16816(float* d, const unsigned* a, const unsigned* b) {
    asm volatile("mma.sync.aligned.m16n8k16.row.col.f32.f16.f16.f32 "
                 "{%0,%1,%2,%3}, {%4,%5,%6,%7}, {%8,%9}, {%0,%1,%2,%3};"
                 : "+f"(d[0]), "+f"(d[1]), "+f"(d[2]), "+f"(d[3])
                 : "r"(a[0]), "r"(a[1]), "r"(a[2]), "r"(a[3]), "r"(b[0]), "r"(b[1]));
}

__device__ __forceinline__ void f16_split(float v, __half& h, __half& l) {
    h = __float2half(v);
    l = __float2half(v - __half2float(h));
}

// ---------------------------------------------------------------------------
// Kernel 1: y[b,i,f] = sum_j adj[b,i,j]*x[b,j,f]; emits y as fp16 hi/lo + deg.
// PROVEN round-9 shape: ICH=32 (512 CTAs), warp owns 4 i-rows, lane owns 4
// features, cp.async double-buffered x tiles + adj row prefetch.
// First 64 blocks (linear id) also convert W -> fp16 (one float4/thread).
// ---------------------------------------------------------------------------
#define ICH 32
#define JT  32
#define FH  128
#define TILE_F4 (JT * FH / 4)
#define NTILES  (NN / JT)

__global__ __launch_bounds__(256) void agg_x_kernel(
    const float* __restrict__ X,
    const float* __restrict__ ADJ,
    const float* __restrict__ W,
    float* __restrict__ DEG)
{
    extern __shared__ float xt[];   // 32 KB

    const int b    = blockIdx.y;
    const int i0   = blockIdx.x * ICH;
    const int fs   = blockIdx.z;
    const int t    = threadIdx.x;
    const int w    = t >> 5;
    const int lane = t & 31;

    // ---- folded W -> fp16 conversion (64 blocks x 256 thr x 1 float4) ----
    {
        const int blin = blockIdx.x + ((int)blockIdx.y << 4) + ((int)blockIdx.z << 8);
        if (blin < (FF * FF / 4) / 256) {
            const int gid = blin * 256 + t;
            float4 w4 = reinterpret_cast<const float4*>(W)[gid];
            __half h[4] = {__float2half(w4.x), __float2half(w4.y),
                           __float2half(w4.z), __float2half(w4.w)};
            *reinterpret_cast<uint2*>(&g_wh[gid * 4]) = *reinterpret_cast<uint2*>(h);
        }
    }

    const float4* xb4 = reinterpret_cast<const float4*>(X + (size_t)b * NN * FF + fs * FH);
    const unsigned sbase = smem_u32(xt);

    ull acc2[4][2] = {{0ull,0ull},{0ull,0ull},{0ull,0ull},{0ull,0ull}};
    int degc[4] = {0, 0, 0, 0};

    const float* adj_base = ADJ + ((size_t)b * NN + i0 + w * 4) * NN + lane;

    auto issue = [&](int jt, int buf) {
#pragma unroll
        for (int p = 0; p < 4; p++) {
            int e   = t + p * 256;
            int row = e >> 5;
            int c   = e & 31;
            cp_async16(sbase + (unsigned)(buf * TILE_F4 + e) * 16u,
                       &xb4[(size_t)(jt * JT + row) * (FF / 4) + c]);
        }
        CP_COMMIT();
    };

    issue(0, 0);
    float av[4];
#pragma unroll
    for (int ii = 0; ii < 4; ii++) av[ii] = adj_base[(size_t)ii * NN];

    for (int jt = 0; jt < NTILES; jt++) {
        const int buf = jt & 1;
        float avn[4] = {0.f, 0.f, 0.f, 0.f};
        if (jt + 1 < NTILES) {
            issue(jt + 1, buf ^ 1);
#pragma unroll
            for (int ii = 0; ii < 4; ii++)
                avn[ii] = adj_base[(size_t)ii * NN + (jt + 1) * JT];
            CP_WAIT(1);
        } else {
            CP_WAIT(0);
        }
        __syncthreads();

        unsigned m[4];
#pragma unroll
        for (int ii = 0; ii < 4; ii++) {
            m[ii] = __ballot_sync(0xffffffffu, av[ii] > 0.0f);
            degc[ii] += __popc(m[ii]);
        }

        const float* tb = xt + buf * (JT * FH) + lane * 4;
        while (m[0] | m[1] | m[2] | m[3]) {
#pragma unroll
            for (int ii = 0; ii < 4; ii++) {
                if (m[ii]) {
                    int j = __ffs(m[ii]) - 1;
                    m[ii] &= m[ii] - 1;
                    float4 h = *reinterpret_cast<const float4*>(tb + j * FH);
                    ull h01, h23;
                    PACK_X2(h01, h.x, h.y);
                    PACK_X2(h23, h.z, h.w);
                    ADD_X2I(acc2[ii][0], h01);
                    ADD_X2I(acc2[ii][1], h23);
                }
            }
        }
#pragma unroll
        for (int ii = 0; ii < 4; ii++) av[ii] = avn[ii];
        __syncthreads();
    }

#pragma unroll
    for (int ii = 0; ii < 4; ii++) {
        const int m_ = b * NN + i0 + w * 4 + ii;
        float o[4];
        UNPK_X2(o[0], o[1], acc2[ii][0]);
        UNPK_X2(o[2], o[3], acc2[ii][1]);
        __half hh[4], ll[4];
#pragma unroll
        for (int q = 0; q < 4; q++) f16_split(o[q], hh[q], ll[q]);
        const size_t off = (size_t)m_ * FF + fs * FH + lane * 4;
        *reinterpret_cast<uint2*>(&g_yh[off]) = *reinterpret_cast<uint2*>(hh);
        *reinterpret_cast<uint2*>(&g_yl[off]) = *reinterpret_cast<uint2*>(ll);
        if (fs == 0 && lane == 0) DEG[m_] = (float)degc[ii];
    }
}

// ---------------------------------------------------------------------------
// Kernel 2: HMMA fp16 GEMM, K=512 logical (yh.wh + yl.wh = y.wh),
// fused gate + blend. 128 CTAs x 512 threads. BM=64, BN=256.
// B (wh, full 256x256 fp16) staged ONCE resident in smem; A staged in 4
// chunks of 128 via double-buffered cp.async.  (16.2us measured, unchanged)
// ---------------------------------------------------------------------------
#define ASTR   272                       // A row stride bytes (128 fp16 + pad)
#define BSTR   528                       // B row stride bytes (256 fp16 + pad)
#define ABUF   (64 * ASTR)               // 17408
#define OFF_A  0
#define OFF_B  (2 * ABUF)                // 34816
#define OFF_GATEP (OFF_B + 256 * BSTR)   // 169984, 8*64 floats
#define OFF_COEFF (OFF_GATEP + 2048)     // 172032, 64 floats
#define SMEM_TOT  (OFF_COEFF + 256)      // 172288

__global__ __launch_bounds__(512, 1) void gemm_mma_kernel(
    const float* __restrict__ Wb,
    const float* __restrict__ DEG,
    const float* __restrict__ X,
    const float* __restrict__ GW,
    const float* __restrict__ GB,
    float* __restrict__ OUT)
{
    extern __shared__ char smem[];
    const unsigned sb = smem_u32(smem);
    const int t    = threadIdx.x;
    const int lane = t & 31;
    const int wid  = t >> 5;             // 0..15
    const int wm   = wid >> 3;           // 0..1  (M warp)
    const int wn   = wid & 7;            // 0..7  (N warp)
    const int m0   = blockIdx.x * 64;

    // ---- stage B once: wh full [256 rows x 256 cols] fp16 ----
#pragma unroll
    for (int p = 0; p < 16; p++) {
        int e   = t + p * 512;           // 0..8191
        int row = e >> 5, u = e & 31;
        cp_async16(sb + OFF_B + row * BSTR + u * 16,
                   &g_wh[(size_t)row * FF + u * 8]);
    }
    CP_COMMIT();

    // stage A chunk c (0..3) into buffer buf
    auto issueA = [&](int c, int buf) {
        const __half* As = (c < 2) ? g_yh : g_yl;
        const int koff = (c & 1) * 128;
#pragma unroll
        for (int p = 0; p < 2; p++) {    // 64 rows x 8 units
            int e = t + p * 512;         // 0..1023
            int row = e >> 4, u = e & 15;
            cp_async16(sb + OFF_A + buf * ABUF + row * ASTR + u * 16,
                       &As[(size_t)(m0 + row) * FF + koff + u * 8]);
        }
        CP_COMMIT();
    };

    float acc[2][4][4];
#pragma unroll
    for (int mf = 0; mf < 2; mf++)
#pragma unroll
        for (int nf = 0; nf < 4; nf++)
#pragma unroll
            for (int q = 0; q < 4; q++) acc[mf][nf][q] = 0.0f;

    issueA(0, 0);
    for (int c = 0; c < 4; c++) {
        const int buf = c & 1;
        if (c + 1 < 4) {
            issueA(c + 1, buf ^ 1);
            CP_WAIT(1);                  // B + A(c) complete, A(c+1) pending
        } else {
            CP_WAIT(0);
        }
        __syncthreads();

        const unsigned aBase = sb + OFF_A + buf * ABUF;
        const unsigned bBase = sb + OFF_B;
        const int koff = (c & 1) * 128;

#pragma unroll
        for (int ks = 0; ks < 8; ks++) {
            const int k0 = ks * 16;
            unsigned a[2][4], b[2][4];
#pragma unroll
            for (int mf = 0; mf < 2; mf++) {
                unsigned addr = aBase
                    + (unsigned)(wm * 32 + mf * 16 + (lane & 15)) * ASTR
                    + (unsigned)(k0 + (lane >> 4) * 8) * 2;
                ldsm_x4(a[mf], addr);
            }
#pragma unroll
            for (int nf2 = 0; nf2 < 2; nf2++) {
                unsigned row = (unsigned)(wn * 32 + nf2 * 16
                                          + ((lane >> 4) & 1) * 8 + (lane & 7));
                unsigned kk  = (unsigned)(koff + k0 + ((lane >> 3) & 1) * 8);
                ldsm_x4(b[nf2], bBase + row * BSTR + kk * 2);
            }
#pragma unroll
            for (int mf = 0; mf < 2; mf++)
#pragma unroll
                for (int nf = 0; nf < 4; nf++)
                    mma16816(acc[mf][nf], a[mf], &b[nf >> 1][(nf & 1) * 2]);
        }
        __syncthreads();   // all warps done with A buf before it is re-filled
    }

    // ---- fused epilogue ----
    const int qr = lane >> 2;            // 0..7 row in frag
    const int qc = (lane & 3) * 2;       // col pair
    float* gatep   = (float*)(smem + OFF_GATEP);   // [8][64]
    float* coeff_s = (float*)(smem + OFF_COEFF);   // [64]

    float2 bias2[4], gh2[4], gx2[4];
#pragma unroll
    for (int nf = 0; nf < 4; nf++) {
        const int n = wn * 32 + nf * 8 + qc;
        bias2[nf] = *reinterpret_cast<const float2*>(&Wb[n]);
        gh2[nf]   = *reinterpret_cast<const float2*>(&GW[FF + n]);
        gx2[nf]   = *reinterpret_cast<const float2*>(&GW[n]);
    }

    float2 xv[2][2][4];
    float gp[2][2] = {{0.f, 0.f}, {0.f, 0.f}};
#pragma unroll
    for (int mf = 0; mf < 2; mf++)
#pragma unroll
        for (int h = 0; h < 2; h++) {
            const int row = wm * 32 + mf * 16 + h * 8 + qr;
            const int m   = m0 + row;
            const float dg = DEG[m];
#pragma unroll
            for (int nf = 0; nf < 4; nf++) {
                const int n = wn * 32 + nf * 8 + qc;
                float v0 = acc[mf][nf][h * 2]     + dg * bias2[nf].x;
                float v1 = acc[mf][nf][h * 2 + 1] + dg * bias2[nf].y;
                v0 = (v0 > 0.0f) ? v0 : 0.2f * v0;
                v1 = (v1 > 0.0f) ? v1 : 0.2f * v1;
                acc[mf][nf][h * 2]     = v0;      // now hp
                acc[mf][nf][h * 2 + 1] = v1;
                float2 x2 = *reinterpret_cast<const float2*>(&X[(size_t)m * FF + n]);
                xv[mf][h][nf] = x2;
                gp[mf][h] += v0 * gh2[nf].x + v1 * gh2[nf].y
                           + x2.x * gx2[nf].x + x2.y * gx2[nf].y;
            }
        }

    // quad reduce (lanes sharing a row)
#pragma unroll
    for (int mf = 0; mf < 2; mf++)
#pragma unroll
        for (int h = 0; h < 2; h++) {
            gp[mf][h] += __shfl_xor_sync(0xffffffffu, gp[mf][h], 1);
            gp[mf][h] += __shfl_xor_sync(0xffffffffu, gp[mf][h], 2);
        }
    if ((lane & 3) == 0) {
#pragma unroll
        for (int mf = 0; mf < 2; mf++)
#pragma unroll
            for (int h = 0; h < 2; h++)
                gatep[wn * 64 + wm * 32 + mf * 16 + h * 8 + qr] = gp[mf][h];
    }
    __syncthreads();

    if (t < 64) {
        float s = GB[0];
#pragma unroll
        for (int i = 0; i < 8; i++) s += gatep[i * 64 + t];
        coeff_s[t] = 1.0f / (1.0f + expf(-s));
    }
    __syncthreads();

#pragma unroll
    for (int mf = 0; mf < 2; mf++)
#pragma unroll
        for (int h = 0; h < 2; h++) {
            const int row = wm * 32 + mf * 16 + h * 8 + qr;
            const int m   = m0 + row;
            const float cf = coeff_s[row];
            const float om = 1.0f - cf;
#pragma unroll
            for (int nf = 0; nf < 4; nf++) {
                const int n = wn * 32 + nf * 8 + qc;
                float2 o;
                o.x = cf * xv[mf][h][nf].x + om * acc[mf][nf][h * 2];
                o.y = cf * xv[mf][h][nf].y + om * acc[mf][nf][h * 2 + 1];
                *reinterpret_cast<float2*>(&OUT[(size_t)m * FF + n]) = o;
            }
        }
}

// ---------------------------------------------------------------------------
extern "C" void kernel_launch(void* const* d_in, const int* in_sizes, int n_in,
                              void* d_out, int out_size)
{
    const float* x    = (const float*)d_in[0];   // [16,512,256]
    const float* adj  = (const float*)d_in[1];   // [16,512,512]
    const float* W_w  = (const float*)d_in[2];   // [256,256]
    const float* W_b  = (const float*)d_in[3];   // [256]
    // d_in[4] = A : dead code in the reference
    const float* gw   = (const float*)d_in[5];   // [1,512]
    const float* gb   = (const float*)d_in[6];   // [1]
    float* out = (float*)d_out;

    float* deg; cudaGetSymbolAddress((void**)&deg, g_deg);

    const int smem1 = 2 * JT * FH * sizeof(float);   // 32 KB
    cudaFuncSetAttribute(agg_x_kernel,
                         cudaFuncAttributeMaxDynamicSharedMemorySize, smem1);
    dim3 grid1(NN / ICH, BB, 2);                     // (16,16,2) = 512 CTAs
    agg_x_kernel<<<grid1, 256, smem1>>>(x, adj, W_w, deg);

    cudaFuncSetAttribute(gemm_mma_kernel,
                         cudaFuncAttributeMaxDynamicSharedMemorySize, SMEM_TOT);
    gemm_mma_kernel<<<M_TOT / 64, 512, SMEM_TOT>>>(W_b, deg, x, gw, gb, out);
}